// round 3
// baseline (speedup 1.0000x reference)
#include <cuda_runtime.h>
#include <math.h>
#include <stdint.h>

#define NN 20000
#define NE 320000
#define NG 64

// ---- scratch (device globals; no allocation allowed) ----
__device__ __align__(16) float g_h  [NN * 256];
__device__ __align__(16) float g_agg[NN * 256];
__device__ __align__(16) float g_t  [NN * 256];
__device__ __align__(16) float g_pool[NG * 256];
__device__ float g_cnt[NG];

// ---------------- PTX helpers ----------------
__device__ __forceinline__ uint32_t cvt_tf32(float x) {
    uint32_t r;
    asm("cvt.rna.tf32.f32 %0, %1;" : "=r"(r) : "f"(x));
    return r;
}

__device__ __forceinline__ void mma8(float* d, const uint32_t* a, const uint32_t* b) {
    asm volatile(
        "mma.sync.aligned.m16n8k8.row.col.f32.tf32.tf32.f32 "
        "{%0,%1,%2,%3}, {%4,%5,%6,%7}, {%8,%9}, {%0,%1,%2,%3};"
        : "+f"(d[0]), "+f"(d[1]), "+f"(d[2]), "+f"(d[3])
        : "r"(a[0]), "r"(a[1]), "r"(a[2]), "r"(a[3]), "r"(b[0]), "r"(b[1]));
}

__device__ __forceinline__ void cp16(uint32_t saddr, const void* gptr) {
    asm volatile("cp.async.cg.shared.global [%0], [%1], 16;" :: "r"(saddr), "l"(gptr));
}
__device__ __forceinline__ void cp_commit() { asm volatile("cp.async.commit_group;"); }

__device__ __forceinline__ void red_add_v2(float* addr, float x, float y) {
    asm volatile("red.global.add.v2.f32 [%0], {%1,%2};"
                 :: "l"(addr), "f"(x), "f"(y) : "memory");
}
__device__ __forceinline__ void red_add_v4(float* addr, float4 v) {
    asm volatile("red.global.add.v4.f32 [%0], {%1,%2,%3,%4};"
                 :: "l"(addr), "f"(v.x), "f"(v.y), "f"(v.z), "f"(v.w) : "memory");
}

__global__ void zero4(float4* p, int n4) {
    int i = blockIdx.x * blockDim.x + threadIdx.x;
    if (i < n4) p[i] = make_float4(0.f, 0.f, 0.f, 0.f);
}
__global__ void copy4(const float4* __restrict__ s, float4* __restrict__ d, int n4) {
    int i = blockIdx.x * blockDim.x + threadIdx.x;
    if (i < n4) d[i] = s[i];
}

// ---- smem strides (floats). Chosen for conflict-free MMA fragment loads. ----
#define AST 20    // A: [128 rows][16 k] stride 20
#define BST 136   // B: [16 k][128 n]  stride 136

__device__ __forceinline__ void stage_load(
    const float* __restrict__ A, const float* __restrict__ W,
    int M, int K, int rowTile, int colTile, int tid, int k0,
    uint32_t abase, uint32_t bbase)
{
    // A: 128 rows x 16 floats = 512 x 16B chunks
    #pragma unroll
    for (int i = 0; i < 2; i++) {
        int slot = tid + (i << 8);
        int m = slot >> 2, seg = slot & 3;
        int gr = rowTile + m; if (gr >= M) gr = M - 1;
        cp16(abase + (uint32_t)(m * AST + seg * 4) * 4,
             A + (size_t)gr * K + k0 + seg * 4);
    }
    // B: 16 k x 128 floats = 512 x 16B chunks
    #pragma unroll
    for (int i = 0; i < 2; i++) {
        int slot = tid + (i << 8);
        int k = slot >> 5, seg = slot & 31;
        cp16(bbase + (uint32_t)(k * BST + seg * 4) * 4,
             W + (size_t)(k0 + k) * 256 + colTile + seg * 4);
    }
}

// ---------------------------------------------------------------------------
// Split-TF32 tensor-core GEMM. CTA tile 128x128 (N=256 via blockIdx.x in {0,1}),
// warp tile 32x64, K-step 16, double-buffered cp.async.
//   PLAIN: C = act(A @ W + bias)
//   EDGE : per row r (edge): msg = relu(acc + bias + h[src[r]]); red.add agg[dst[r]]
// ---------------------------------------------------------------------------
template<bool RELU, bool EDGE>
__global__ __launch_bounds__(256)
void mma_gemm(const float* __restrict__ A, const float* __restrict__ W,
              const float* __restrict__ bias, float* __restrict__ C,
              const int* __restrict__ ei, const float* __restrict__ hg,
              float* __restrict__ agg, int M, int K)
{
    __shared__ float As[2][128 * AST];
    __shared__ float Bs[2][16 * BST];

    const int tid  = threadIdx.x;
    const int lane = tid & 31;
    const int wid  = tid >> 5;
    const int g    = lane >> 2;   // groupID
    const int tig  = lane & 3;    // threadID_in_group
    const int wm   = wid & 3;     // warp row (4 x 32)
    const int wn   = wid >> 2;    // warp col (2 x 64)
    const int rowTile = blockIdx.y * 128;
    const int colTile = blockIdx.x * 128;

    float acc[2][8][4];
    #pragma unroll
    for (int mt = 0; mt < 2; mt++)
        #pragma unroll
        for (int nt = 0; nt < 8; nt++)
            #pragma unroll
            for (int j = 0; j < 4; j++) acc[mt][nt][j] = 0.f;

    const int S = K >> 4;

    uint32_t ab[2], bb[2];
    ab[0] = (uint32_t)__cvta_generic_to_shared(&As[0][0]);
    ab[1] = (uint32_t)__cvta_generic_to_shared(&As[1][0]);
    bb[0] = (uint32_t)__cvta_generic_to_shared(&Bs[0][0]);
    bb[1] = (uint32_t)__cvta_generic_to_shared(&Bs[1][0]);

    stage_load(A, W, M, K, rowTile, colTile, tid, 0, ab[0], bb[0]);
    cp_commit();

    for (int s = 0; s < S; s++) {
        const int buf = s & 1;
        if (s + 1 < S) {
            stage_load(A, W, M, K, rowTile, colTile, tid, (s + 1) << 4,
                       ab[buf ^ 1], bb[buf ^ 1]);
            cp_commit();
            asm volatile("cp.async.wait_group 1;");
        } else {
            asm volatile("cp.async.wait_group 0;");
        }
        __syncthreads();

        const float* as = As[buf];
        const float* bs = Bs[buf];

        #pragma unroll
        for (int k8 = 0; k8 < 2; k8++) {
            const int kk = k8 * 8;
            uint32_t ah[2][4], al[2][4];
            #pragma unroll
            for (int mt = 0; mt < 2; mt++)
                #pragma unroll
                for (int j = 0; j < 4; j++) {
                    int m = wm * 32 + mt * 16 + g + ((j & 1) << 3);
                    int k = kk + tig + ((j >> 1) << 2);
                    float v = as[m * AST + k];
                    uint32_t hi = cvt_tf32(v);
                    ah[mt][j] = hi;
                    al[mt][j] = cvt_tf32(v - __uint_as_float(hi));
                }
            uint32_t bh[8][2], bl[8][2];
            #pragma unroll
            for (int nt = 0; nt < 8; nt++)
                #pragma unroll
                for (int j = 0; j < 2; j++) {
                    int k = kk + tig + (j << 2);
                    int n = wn * 64 + nt * 8 + g;
                    float v = bs[k * BST + n];
                    uint32_t hi = cvt_tf32(v);
                    bh[nt][j] = hi;
                    bl[nt][j] = cvt_tf32(v - __uint_as_float(hi));
                }
            #pragma unroll
            for (int mt = 0; mt < 2; mt++)
                #pragma unroll
                for (int nt = 0; nt < 8; nt++) {
                    mma8(acc[mt][nt], ah[mt], bh[nt]);
                    mma8(acc[mt][nt], ah[mt], bl[nt]);
                    mma8(acc[mt][nt], al[mt], bh[nt]);
                }
        }
        __syncthreads();
    }

    // ---------------- epilogue ----------------
    #pragma unroll
    for (int mt = 0; mt < 2; mt++) {
        const int r0 = rowTile + wm * 32 + mt * 16 + g;
        const int r1 = r0 + 8;
        if (EDGE) {
            if (r0 < M) {
                const int s0 = ei[r0], d0 = ei[NE + r0];
                const int s1 = ei[r1], d1 = ei[NE + r1];
                #pragma unroll
                for (int nt = 0; nt < 8; nt++) {
                    const int col = colTile + wn * 64 + nt * 8 + tig * 2;
                    float2 bv = *(const float2*)(bias + col);
                    float2 h0 = *(const float2*)(hg + (size_t)s0 * 256 + col);
                    float2 h1 = *(const float2*)(hg + (size_t)s1 * 256 + col);
                    float v0x = fmaxf(acc[mt][nt][0] + bv.x + h0.x, 0.f);
                    float v0y = fmaxf(acc[mt][nt][1] + bv.y + h0.y, 0.f);
                    float v1x = fmaxf(acc[mt][nt][2] + bv.x + h1.x, 0.f);
                    float v1y = fmaxf(acc[mt][nt][3] + bv.y + h1.y, 0.f);
                    red_add_v2(agg + (size_t)d0 * 256 + col, v0x, v0y);
                    red_add_v2(agg + (size_t)d1 * 256 + col, v1x, v1y);
                }
            }
        } else {
            #pragma unroll
            for (int nt = 0; nt < 8; nt++) {
                const int col = colTile + wn * 64 + nt * 8 + tig * 2;
                float2 bv = *(const float2*)(bias + col);
                if (r0 < M) {
                    float2 v;
                    v.x = acc[mt][nt][0] + bv.x;
                    v.y = acc[mt][nt][1] + bv.y;
                    if (RELU) { v.x = fmaxf(v.x, 0.f); v.y = fmaxf(v.y, 0.f); }
                    *(float2*)(C + (size_t)r0 * 256 + col) = v;
                }
                if (r1 < M) {
                    float2 v;
                    v.x = acc[mt][nt][2] + bv.x;
                    v.y = acc[mt][nt][3] + bv.y;
                    if (RELU) { v.x = fmaxf(v.x, 0.f); v.y = fmaxf(v.y, 0.f); }
                    *(float2*)(C + (size_t)r1 * 256 + col) = v;
                }
            }
        }
    }
}

// One block (64 threads) per node: scatter mean-pool contributions.
__global__ void pool_kernel(const float* __restrict__ h,
                            const int* __restrict__ batch,
                            float* __restrict__ pool, float* __restrict__ cnt)
{
    const int node = blockIdx.x;
    const int gph = batch[node];
    const int t = threadIdx.x;  // 0..63
    float4 v = *reinterpret_cast<const float4*>(h + (size_t)node * 256 + t * 4);
    red_add_v4(pool + (size_t)gph * 256 + t * 4, v);
    if (t == 0) atomicAdd(cnt + gph, 1.0f);
}

// One block per graph: mean -> relu(g@W1+b1)@W2+b2 -> L2 normalize.
__global__ void final_kernel(const float* __restrict__ pool,
                             const float* __restrict__ cnt,
                             const float* __restrict__ W1, const float* __restrict__ b1,
                             const float* __restrict__ W2, const float* __restrict__ b2,
                             float* __restrict__ out)
{
    const int gph = blockIdx.x;
    const int j = threadIdx.x;  // 0..255
    __shared__ float s[256];
    __shared__ float s2[256];
    __shared__ float redbuf[8];
    __shared__ float snorm;

    const float inv = 1.0f / fmaxf(cnt[gph], 1.0f);
    s[j] = pool[gph * 256 + j] * inv;
    __syncthreads();

    float t = b1[j];
    #pragma unroll 8
    for (int k = 0; k < 256; k++) t = fmaf(s[k], W1[k * 256 + j], t);
    t = fmaxf(t, 0.f);
    s2[j] = t;
    __syncthreads();

    float o = b2[j];
    #pragma unroll 8
    for (int k = 0; k < 256; k++) o = fmaf(s2[k], W2[k * 256 + j], o);

    float sq = o * o;
    #pragma unroll
    for (int off = 16; off > 0; off >>= 1)
        sq += __shfl_down_sync(0xffffffffu, sq, off);
    if ((j & 31) == 0) redbuf[j >> 5] = sq;
    __syncthreads();
    if (j == 0) {
        float ss = 0.f;
        #pragma unroll
        for (int w = 0; w < 8; w++) ss += redbuf[w];
        snorm = fmaxf(sqrtf(ss), 1e-12f);
    }
    __syncthreads();

    out[gph * 256 + j] = o / snorm;
}

extern "C" void kernel_launch(void* const* d_in, const int* in_sizes, int n_in,
                              void* d_out, int out_size)
{
    const float* x   = (const float*)d_in[0];
    const int*   ei  = (const int*)  d_in[1];
    const float* ea  = (const float*)d_in[2];
    const int*   bi  = (const int*)  d_in[3];
    const float* xW  = (const float*)d_in[4];
    const float* xb  = (const float*)d_in[5];
    const float* eW  = (const float*)d_in[6];
    const float* eb  = (const float*)d_in[7];
    const float* W1  = (const float*)d_in[8];
    const float* b1  = (const float*)d_in[9];
    const float* W2  = (const float*)d_in[10];
    const float* b2  = (const float*)d_in[11];
    const float* oW1 = (const float*)d_in[12];
    const float* ob1 = (const float*)d_in[13];
    const float* oW2 = (const float*)d_in[14];
    const float* ob2 = (const float*)d_in[15];
    float* out = (float*)d_out;

    float *ph, *pagg, *pt, *ppool, *pcnt;
    cudaGetSymbolAddress((void**)&ph,    g_h);
    cudaGetSymbolAddress((void**)&pagg,  g_agg);
    cudaGetSymbolAddress((void**)&pt,    g_t);
    cudaGetSymbolAddress((void**)&ppool, g_pool);
    cudaGetSymbolAddress((void**)&pcnt,  g_cnt);

    dim3 gNode(2, (NN + 127) / 128);   // (2, 157)
    dim3 gEdge(2, NE / 128);           // (2, 2500)

    // h = x @ xproj_W + xproj_b   (K = 128)
    mma_gemm<false, false><<<gNode, 256>>>(
        x, xW, xb, ph, nullptr, nullptr, nullptr, NN, 128);

    for (int l = 0; l < 3; l++) {
        // agg = h  (folds the "+ x_i" of GIN into the scatter target)
        copy4<<<(NN * 64 + 255) / 256, 256>>>((const float4*)ph, (float4*)pagg, NN * 64);
        // fused: proj = ea @ eW[l] + eb[l]; msg = relu(h[src] + proj); agg[dst] += msg
        mma_gemm<false, true><<<gEdge, 256>>>(
            ea, eW + l * 64 * 256, eb + l * 256, nullptr, ei, ph, pagg, NE, 64);
        // t = relu(agg @ W1 + b1)   (K = 256)
        mma_gemm<true, false><<<gNode, 256>>>(
            pagg, W1 + l * 256 * 256, b1 + l * 256, pt, nullptr, nullptr, nullptr, NN, 256);
        // h = relu(t @ W2 + b2)
        mma_gemm<true, false><<<gNode, 256>>>(
            pt, W2 + l * 256 * 256, b2 + l * 256, ph, nullptr, nullptr, nullptr, NN, 256);
    }

    // mean pool
    zero4<<<(NG * 64 + 255) / 256, 256>>>((float4*)ppool, NG * 64);
    zero4<<<1, 256>>>((float4*)pcnt, NG / 4);
    pool_kernel<<<NN, 64>>>(ph, bi, ppool, pcnt);

    // graph head + normalize
    final_kernel<<<NG, 256>>>(ppool, pcnt, oW1, ob1, oW2, ob2, out);
}

// round 4
// speedup vs baseline: 1.1683x; 1.1683x over previous
#include <cuda_runtime.h>
#include <math.h>
#include <stdint.h>

#define NN 20000
#define NE 320000
#define NG 64

// ---- scratch (device globals; no allocation allowed) ----
__device__ __align__(16) float g_h  [NN * 256];
__device__ __align__(16) float g_agg[NN * 256];
__device__ __align__(16) float g_t  [NN * 256];
__device__ __align__(16) float g_pool[NG * 256];
__device__ float g_cnt[NG];

// ---------------- PTX helpers ----------------
__device__ __forceinline__ uint32_t cvt_tf32(float x) {
    uint32_t r;
    asm("cvt.rna.tf32.f32 %0, %1;" : "=r"(r) : "f"(x));
    return r;
}

__device__ __forceinline__ void mma8(float* d, const uint32_t* a, const uint32_t* b) {
    asm volatile(
        "mma.sync.aligned.m16n8k8.row.col.f32.tf32.tf32.f32 "
        "{%0,%1,%2,%3}, {%4,%5,%6,%7}, {%8,%9}, {%0,%1,%2,%3};"
        : "+f"(d[0]), "+f"(d[1]), "+f"(d[2]), "+f"(d[3])
        : "r"(a[0]), "r"(a[1]), "r"(a[2]), "r"(a[3]), "r"(b[0]), "r"(b[1]));
}

__device__ __forceinline__ void cp16(uint32_t saddr, const void* gptr) {
    asm volatile("cp.async.cg.shared.global [%0], [%1], 16;" :: "r"(saddr), "l"(gptr));
}
__device__ __forceinline__ void cp_commit() { asm volatile("cp.async.commit_group;"); }

__device__ __forceinline__ void red_add_v4(float* addr, float4 v) {
    asm volatile("red.global.add.v4.f32 [%0], {%1,%2,%3,%4};"
                 :: "l"(addr), "f"(v.x), "f"(v.y), "f"(v.z), "f"(v.w) : "memory");
}

__global__ void zero4(float4* p, int n4) {
    int i = blockIdx.x * blockDim.x + threadIdx.x;
    if (i < n4) p[i] = make_float4(0.f, 0.f, 0.f, 0.f);
}
__global__ void copy4(const float4* __restrict__ s, float4* __restrict__ d, int n4) {
    int i = blockIdx.x * blockDim.x + threadIdx.x;
    if (i < n4) d[i] = s[i];
}

// ---- smem strides (floats). Conflict-free for MMA fragment loads. ----
#define AST 20    // A: [rows][16 k] stride 20
#define BST 136   // B: [16 k][128 n] stride 136

// ---------------------------------------------------------------------------
// Node GEMM (unchanged from R3): CTA tile 128x128, warp tile 32x64.
// ---------------------------------------------------------------------------
template<bool RELU>
__global__ __launch_bounds__(256)
void mma_gemm(const float* __restrict__ A, const float* __restrict__ W,
              const float* __restrict__ bias, float* __restrict__ C,
              int M, int K)
{
    __shared__ float As[2][128 * AST];
    __shared__ float Bs[2][16 * BST];

    const int tid  = threadIdx.x;
    const int lane = tid & 31;
    const int wid  = tid >> 5;
    const int g    = lane >> 2;
    const int tig  = lane & 3;
    const int wm   = wid & 3;
    const int wn   = wid >> 2;
    const int rowTile = blockIdx.y * 128;
    const int colTile = blockIdx.x * 128;

    float acc[2][8][4];
    #pragma unroll
    for (int mt = 0; mt < 2; mt++)
        #pragma unroll
        for (int nt = 0; nt < 8; nt++)
            #pragma unroll
            for (int j = 0; j < 4; j++) acc[mt][nt][j] = 0.f;

    const int S = K >> 4;

    uint32_t ab[2], bb[2];
    ab[0] = (uint32_t)__cvta_generic_to_shared(&As[0][0]);
    ab[1] = (uint32_t)__cvta_generic_to_shared(&As[1][0]);
    bb[0] = (uint32_t)__cvta_generic_to_shared(&Bs[0][0]);
    bb[1] = (uint32_t)__cvta_generic_to_shared(&Bs[1][0]);

    auto stage = [&](int k0, uint32_t abase, uint32_t bbase) {
        #pragma unroll
        for (int i = 0; i < 2; i++) {
            int slot = tid + (i << 8);
            int m = slot >> 2, seg = slot & 3;
            int gr = rowTile + m; if (gr >= M) gr = M - 1;
            cp16(abase + (uint32_t)(m * AST + seg * 4) * 4,
                 A + (size_t)gr * K + k0 + seg * 4);
        }
        #pragma unroll
        for (int i = 0; i < 2; i++) {
            int slot = tid + (i << 8);
            int k = slot >> 5, seg = slot & 31;
            cp16(bbase + (uint32_t)(k * BST + seg * 4) * 4,
                 W + (size_t)(k0 + k) * 256 + colTile + seg * 4);
        }
    };

    stage(0, ab[0], bb[0]);
    cp_commit();

    for (int s = 0; s < S; s++) {
        const int buf = s & 1;
        if (s + 1 < S) {
            stage((s + 1) << 4, ab[buf ^ 1], bb[buf ^ 1]);
            cp_commit();
            asm volatile("cp.async.wait_group 1;");
        } else {
            asm volatile("cp.async.wait_group 0;");
        }
        __syncthreads();

        const float* as = As[buf];
        const float* bs = Bs[buf];

        #pragma unroll
        for (int k8 = 0; k8 < 2; k8++) {
            const int kk = k8 * 8;
            uint32_t ah[2][4], al[2][4];
            #pragma unroll
            for (int mt = 0; mt < 2; mt++)
                #pragma unroll
                for (int j = 0; j < 4; j++) {
                    int m = wm * 32 + mt * 16 + g + ((j & 1) << 3);
                    int k = kk + tig + ((j >> 1) << 2);
                    float v = as[m * AST + k];
                    uint32_t hi = cvt_tf32(v);
                    ah[mt][j] = hi;
                    al[mt][j] = cvt_tf32(v - __uint_as_float(hi));
                }
            uint32_t bh[8][2], bl[8][2];
            #pragma unroll
            for (int nt = 0; nt < 8; nt++)
                #pragma unroll
                for (int j = 0; j < 2; j++) {
                    int k = kk + tig + (j << 2);
                    int n = wn * 64 + nt * 8 + g;
                    float v = bs[k * BST + n];
                    uint32_t hi = cvt_tf32(v);
                    bh[nt][j] = hi;
                    bl[nt][j] = cvt_tf32(v - __uint_as_float(hi));
                }
            #pragma unroll
            for (int mt = 0; mt < 2; mt++)
                #pragma unroll
                for (int nt = 0; nt < 8; nt++) {
                    mma8(acc[mt][nt], ah[mt], bh[nt]);
                    mma8(acc[mt][nt], ah[mt], bl[nt]);
                    mma8(acc[mt][nt], al[mt], bh[nt]);
                }
        }
        __syncthreads();
    }

    #pragma unroll
    for (int mt = 0; mt < 2; mt++) {
        const int r0 = rowTile + wm * 32 + mt * 16 + g;
        const int r1 = r0 + 8;
        #pragma unroll
        for (int nt = 0; nt < 8; nt++) {
            const int col = colTile + wn * 64 + nt * 8 + tig * 2;
            float2 bv = *(const float2*)(bias + col);
            if (r0 < M) {
                float2 v;
                v.x = acc[mt][nt][0] + bv.x;
                v.y = acc[mt][nt][1] + bv.y;
                if (RELU) { v.x = fmaxf(v.x, 0.f); v.y = fmaxf(v.y, 0.f); }
                *(float2*)(C + (size_t)r0 * 256 + col) = v;
            }
            if (r1 < M) {
                float2 v;
                v.x = acc[mt][nt][2] + bv.x;
                v.y = acc[mt][nt][3] + bv.y;
                if (RELU) { v.x = fmaxf(v.x, 0.f); v.y = fmaxf(v.y, 0.f); }
                *(float2*)(C + (size_t)r1 * 256 + col) = v;
            }
        }
    }
}

// ---------------------------------------------------------------------------
// Edge-fused GEMM: CTA tile 64(M) x 128(N), K=64, warp tile 16x64.
// 2 CTAs/SM for latency hiding. Epilogue: pair adjacent lanes via shfl so
// even lanes do float4 gathers + red.global.add.v4 scatters.
//   per edge row r: msg = relu(acc + bias + h[src[r]]); agg[dst[r]] += msg
// ---------------------------------------------------------------------------
__global__ __launch_bounds__(256, 2)
void edge_gemm(const float* __restrict__ A, const float* __restrict__ W,
               const float* __restrict__ bias,
               const int* __restrict__ ei, const float* __restrict__ hg,
               float* __restrict__ agg)
{
    __shared__ float As[2][64 * AST];
    __shared__ float Bs[2][16 * BST];

    const int tid  = threadIdx.x;
    const int lane = tid & 31;
    const int wid  = tid >> 5;
    const int g    = lane >> 2;
    const int tig  = lane & 3;
    const int wm   = wid & 3;     // 4 warps x 16 rows
    const int wn   = wid >> 2;    // 2 warps x 64 cols
    const int rowTile = blockIdx.y * 64;
    const int colTile = blockIdx.x * 128;

    float acc[8][4];
    #pragma unroll
    for (int nt = 0; nt < 8; nt++)
        #pragma unroll
        for (int j = 0; j < 4; j++) acc[nt][j] = 0.f;

    uint32_t ab[2], bb[2];
    ab[0] = (uint32_t)__cvta_generic_to_shared(&As[0][0]);
    ab[1] = (uint32_t)__cvta_generic_to_shared(&As[1][0]);
    bb[0] = (uint32_t)__cvta_generic_to_shared(&Bs[0][0]);
    bb[1] = (uint32_t)__cvta_generic_to_shared(&Bs[1][0]);

    auto stage = [&](int k0, uint32_t abase, uint32_t bbase) {
        // A: 64 rows x 16 k = 256 chunks -> 1 per thread
        {
            int m = tid >> 2, seg = tid & 3;
            cp16(abase + (uint32_t)(m * AST + seg * 4) * 4,
                 A + (size_t)(rowTile + m) * 64 + k0 + seg * 4);
        }
        // B: 16 k x 128 n = 512 chunks -> 2 per thread
        #pragma unroll
        for (int i = 0; i < 2; i++) {
            int slot = tid + (i << 8);
            int k = slot >> 5, seg = slot & 31;
            cp16(bbase + (uint32_t)(k * BST + seg * 4) * 4,
                 W + (size_t)(k0 + k) * 256 + colTile + seg * 4);
        }
    };

    stage(0, ab[0], bb[0]);
    cp_commit();

    #pragma unroll
    for (int s = 0; s < 4; s++) {   // K = 64 -> 4 steps of 16
        const int buf = s & 1;
        if (s + 1 < 4) {
            stage((s + 1) << 4, ab[buf ^ 1], bb[buf ^ 1]);
            cp_commit();
            asm volatile("cp.async.wait_group 1;");
        } else {
            asm volatile("cp.async.wait_group 0;");
        }
        __syncthreads();

        const float* as = As[buf];
        const float* bs = Bs[buf];

        #pragma unroll
        for (int k8 = 0; k8 < 2; k8++) {
            const int kk = k8 * 8;
            uint32_t ah[4], al[4];
            #pragma unroll
            for (int j = 0; j < 4; j++) {
                int m = wm * 16 + g + ((j & 1) << 3);
                int k = kk + tig + ((j >> 1) << 2);
                float v = as[m * AST + k];
                uint32_t hi = cvt_tf32(v);
                ah[j] = hi;
                al[j] = cvt_tf32(v - __uint_as_float(hi));
            }
            uint32_t bh[8][2], bl[8][2];
            #pragma unroll
            for (int nt = 0; nt < 8; nt++)
                #pragma unroll
                for (int j = 0; j < 2; j++) {
                    int k = kk + tig + (j << 2);
                    int n = wn * 64 + nt * 8 + g;
                    float v = bs[k * BST + n];
                    uint32_t hi = cvt_tf32(v);
                    bh[nt][j] = hi;
                    bl[nt][j] = cvt_tf32(v - __uint_as_float(hi));
                }
            #pragma unroll
            for (int nt = 0; nt < 8; nt++) {
                mma8(acc[nt], ah, bh[nt]);
                mma8(acc[nt], ah, bl[nt]);
                mma8(acc[nt], al, bh[nt]);
            }
        }
        __syncthreads();
    }

    // ---------------- fused epilogue ----------------
    const int r0 = rowTile + wm * 16 + g;
    const int r1 = r0 + 8;
    const int s0 = ei[r0],  d0 = ei[NE + r0];
    const int s1 = ei[r1],  d1 = ei[NE + r1];
    const bool even = (tig & 1) == 0;

    #pragma unroll
    for (int nt = 0; nt < 8; nt++) {
        const int col = colTile + wn * 64 + nt * 8 + tig * 2;
        // row r0: lanes tig,tig^1 pair up; even lane owns cols [col, col+4)
        float px0 = __shfl_xor_sync(0xffffffffu, acc[nt][0], 1);
        float py0 = __shfl_xor_sync(0xffffffffu, acc[nt][1], 1);
        float px1 = __shfl_xor_sync(0xffffffffu, acc[nt][2], 1);
        float py1 = __shfl_xor_sync(0xffffffffu, acc[nt][3], 1);
        if (even) {
            float4 bv = *(const float4*)(bias + col);
            float4 h0 = *(const float4*)(hg + (size_t)s0 * 256 + col);
            float4 v0;
            v0.x = fmaxf(acc[nt][0] + bv.x + h0.x, 0.f);
            v0.y = fmaxf(acc[nt][1] + bv.y + h0.y, 0.f);
            v0.z = fmaxf(px0        + bv.z + h0.z, 0.f);
            v0.w = fmaxf(py0        + bv.w + h0.w, 0.f);
            red_add_v4(agg + (size_t)d0 * 256 + col, v0);

            float4 h1 = *(const float4*)(hg + (size_t)s1 * 256 + col);
            float4 v1;
            v1.x = fmaxf(acc[nt][2] + bv.x + h1.x, 0.f);
            v1.y = fmaxf(acc[nt][3] + bv.y + h1.y, 0.f);
            v1.z = fmaxf(px1        + bv.z + h1.z, 0.f);
            v1.w = fmaxf(py1        + bv.w + h1.w, 0.f);
            red_add_v4(agg + (size_t)d1 * 256 + col, v1);
        }
    }
}

// One block (64 threads) per node: scatter mean-pool contributions.
__global__ void pool_kernel(const float* __restrict__ h,
                            const int* __restrict__ batch,
                            float* __restrict__ pool, float* __restrict__ cnt)
{
    const int node = blockIdx.x;
    const int gph = batch[node];
    const int t = threadIdx.x;  // 0..63
    float4 v = *reinterpret_cast<const float4*>(h + (size_t)node * 256 + t * 4);
    red_add_v4(pool + (size_t)gph * 256 + t * 4, v);
    if (t == 0) atomicAdd(cnt + gph, 1.0f);
}

// One block per graph: mean -> relu(g@W1+b1)@W2+b2 -> L2 normalize.
__global__ void final_kernel(const float* __restrict__ pool,
                             const float* __restrict__ cnt,
                             const float* __restrict__ W1, const float* __restrict__ b1,
                             const float* __restrict__ W2, const float* __restrict__ b2,
                             float* __restrict__ out)
{
    const int gph = blockIdx.x;
    const int j = threadIdx.x;  // 0..255
    __shared__ float s[256];
    __shared__ float s2[256];
    __shared__ float redbuf[8];
    __shared__ float snorm;

    const float inv = 1.0f / fmaxf(cnt[gph], 1.0f);
    s[j] = pool[gph * 256 + j] * inv;
    __syncthreads();

    float t = b1[j];
    #pragma unroll 8
    for (int k = 0; k < 256; k++) t = fmaf(s[k], W1[k * 256 + j], t);
    t = fmaxf(t, 0.f);
    s2[j] = t;
    __syncthreads();

    float o = b2[j];
    #pragma unroll 8
    for (int k = 0; k < 256; k++) o = fmaf(s2[k], W2[k * 256 + j], o);

    float sq = o * o;
    #pragma unroll
    for (int off = 16; off > 0; off >>= 1)
        sq += __shfl_down_sync(0xffffffffu, sq, off);
    if ((j & 31) == 0) redbuf[j >> 5] = sq;
    __syncthreads();
    if (j == 0) {
        float ss = 0.f;
        #pragma unroll
        for (int w = 0; w < 8; w++) ss += redbuf[w];
        snorm = fmaxf(sqrtf(ss), 1e-12f);
    }
    __syncthreads();

    out[gph * 256 + j] = o / snorm;
}

extern "C" void kernel_launch(void* const* d_in, const int* in_sizes, int n_in,
                              void* d_out, int out_size)
{
    const float* x   = (const float*)d_in[0];
    const int*   ei  = (const int*)  d_in[1];
    const float* ea  = (const float*)d_in[2];
    const int*   bi  = (const int*)  d_in[3];
    const float* xW  = (const float*)d_in[4];
    const float* xb  = (const float*)d_in[5];
    const float* eW  = (const float*)d_in[6];
    const float* eb  = (const float*)d_in[7];
    const float* W1  = (const float*)d_in[8];
    const float* b1  = (const float*)d_in[9];
    const float* W2  = (const float*)d_in[10];
    const float* b2  = (const float*)d_in[11];
    const float* oW1 = (const float*)d_in[12];
    const float* ob1 = (const float*)d_in[13];
    const float* oW2 = (const float*)d_in[14];
    const float* ob2 = (const float*)d_in[15];
    float* out = (float*)d_out;

    float *ph, *pagg, *pt, *ppool, *pcnt;
    cudaGetSymbolAddress((void**)&ph,    g_h);
    cudaGetSymbolAddress((void**)&pagg,  g_agg);
    cudaGetSymbolAddress((void**)&pt,    g_t);
    cudaGetSymbolAddress((void**)&ppool, g_pool);
    cudaGetSymbolAddress((void**)&pcnt,  g_cnt);

    dim3 gNode(2, (NN + 127) / 128);   // (2, 157)
    dim3 gEdge(2, NE / 64);            // (2, 5000)

    // h = x @ xproj_W + xproj_b   (K = 128)
    mma_gemm<false><<<gNode, 256>>>(x, xW, xb, ph, NN, 128);

    for (int l = 0; l < 3; l++) {
        // agg = h  (folds the "+ x_i" of GIN into the scatter target)
        copy4<<<(NN * 64 + 255) / 256, 256>>>((const float4*)ph, (float4*)pagg, NN * 64);
        // fused: proj = ea @ eW[l] + eb[l]; msg = relu(h[src] + proj); agg[dst] += msg
        edge_gemm<<<gEdge, 256>>>(ea, eW + l * 64 * 256, eb + l * 256, ei, ph, pagg);
        // t = relu(agg @ W1 + b1)   (K = 256)
        mma_gemm<true><<<gNode, 256>>>(pagg, W1 + l * 256 * 256, b1 + l * 256, pt, NN, 256);
        // h = relu(t @ W2 + b2)
        mma_gemm<true><<<gNode, 256>>>(pt, W2 + l * 256 * 256, b2 + l * 256, ph, NN, 256);
    }

    // mean pool
    zero4<<<(NG * 64 + 255) / 256, 256>>>((float4*)ppool, NG * 64);
    zero4<<<1, 256>>>((float4*)pcnt, NG / 4);
    pool_kernel<<<NN, 64>>>(ph, bi, ppool, pcnt);

    // graph head + normalize
    final_kernel<<<NG, 256>>>(ppool, pcnt, oW1, ob1, oW2, ob2, out);
}

// round 5
// speedup vs baseline: 1.2438x; 1.0647x over previous
#include <cuda_runtime.h>
#include <math.h>
#include <stdint.h>

#define NN 20000
#define NE 320000
#define NG 64

// ---- scratch (device globals; no allocation allowed) ----
__device__ __align__(16) float g_h  [NN * 256];
__device__ __align__(16) float g_agg[NN * 256];
__device__ __align__(16) float g_t  [NN * 256];
__device__ __align__(16) float g_pool[NG * 256];
__device__ float g_cnt[NG];
__device__ __align__(16) int g_histo[NN];   // counts -> scatter cursor
__device__ __align__(16) int g_perm[NE];    // edges sorted by dst

// ---------------- PTX helpers ----------------
__device__ __forceinline__ uint32_t cvt_tf32(float x) {
    uint32_t r;
    asm("cvt.rna.tf32.f32 %0, %1;" : "=r"(r) : "f"(x));
    return r;
}

__device__ __forceinline__ void mma8(float* d, const uint32_t* a, const uint32_t* b) {
    asm volatile(
        "mma.sync.aligned.m16n8k8.row.col.f32.tf32.tf32.f32 "
        "{%0,%1,%2,%3}, {%4,%5,%6,%7}, {%8,%9}, {%0,%1,%2,%3};"
        : "+f"(d[0]), "+f"(d[1]), "+f"(d[2]), "+f"(d[3])
        : "r"(a[0]), "r"(a[1]), "r"(a[2]), "r"(a[3]), "r"(b[0]), "r"(b[1]));
}

__device__ __forceinline__ void cp16(uint32_t saddr, const void* gptr) {
    asm volatile("cp.async.cg.shared.global [%0], [%1], 16;" :: "r"(saddr), "l"(gptr));
}
__device__ __forceinline__ void cp_commit() { asm volatile("cp.async.commit_group;"); }

__device__ __forceinline__ void red_add_v4(float* addr, float4 v) {
    asm volatile("red.global.add.v4.f32 [%0], {%1,%2,%3,%4};"
                 :: "l"(addr), "f"(v.x), "f"(v.y), "f"(v.z), "f"(v.w) : "memory");
}

__global__ void zero4(float4* p, int n4) {
    int i = blockIdx.x * blockDim.x + threadIdx.x;
    if (i < n4) p[i] = make_float4(0.f, 0.f, 0.f, 0.f);
}
__global__ void copy4(const float4* __restrict__ s, float4* __restrict__ d, int n4) {
    int i = blockIdx.x * blockDim.x + threadIdx.x;
    if (i < n4) d[i] = s[i];
}

// ---------------- counting sort of edges by dst ----------------
__global__ void hist_kernel(const int* __restrict__ ei, int* __restrict__ histo) {
    int e = blockIdx.x * blockDim.x + threadIdx.x;
    if (e < NE) atomicAdd(&histo[ei[NE + e]], 1);
}

__global__ void scan_kernel(int* __restrict__ histo) {
    __shared__ int s[256];
    const int t = threadIdx.x;
    const int CH = (NN + 255) / 256;   // 79
    const int base = t * CH;
    int sum = 0;
    for (int i = 0; i < CH; i++) {
        int idx = base + i;
        if (idx < NN) sum += histo[idx];
    }
    s[t] = sum;
    __syncthreads();
    // Hillis-Steele inclusive scan
    for (int d = 1; d < 256; d <<= 1) {
        int add = (t >= d) ? s[t - d] : 0;
        __syncthreads();
        s[t] += add;
        __syncthreads();
    }
    int run = s[t] - sum;   // exclusive prefix for this chunk
    for (int i = 0; i < CH; i++) {
        int idx = base + i;
        if (idx < NN) {
            int c = histo[idx];
            histo[idx] = run;   // becomes scatter cursor
            run += c;
        }
    }
}

__global__ void scatter_kernel(const int* __restrict__ ei,
                               int* __restrict__ histo, int* __restrict__ perm) {
    int e = blockIdx.x * blockDim.x + threadIdx.x;
    if (e < NE) {
        int pos = atomicAdd(&histo[ei[NE + e]], 1);
        perm[pos] = e;
    }
}

// ---- smem strides (floats). Conflict-free for MMA fragment loads. ----
#define AST 20    // A: [rows][16 k] stride 20
#define BST 136   // B: [16 k][128 n] stride 136

// ---------------------------------------------------------------------------
// Node GEMM: CTA tile 128x128, warp tile 32x64, split-TF32, double buffered.
// ---------------------------------------------------------------------------
template<bool RELU>
__global__ __launch_bounds__(256)
void mma_gemm(const float* __restrict__ A, const float* __restrict__ W,
              const float* __restrict__ bias, float* __restrict__ C,
              int M, int K)
{
    __shared__ float As[2][128 * AST];
    __shared__ float Bs[2][16 * BST];

    const int tid  = threadIdx.x;
    const int lane = tid & 31;
    const int wid  = tid >> 5;
    const int g    = lane >> 2;
    const int tig  = lane & 3;
    const int wm   = wid & 3;
    const int wn   = wid >> 2;
    const int rowTile = blockIdx.y * 128;
    const int colTile = blockIdx.x * 128;

    float acc[2][8][4];
    #pragma unroll
    for (int mt = 0; mt < 2; mt++)
        #pragma unroll
        for (int nt = 0; nt < 8; nt++)
            #pragma unroll
            for (int j = 0; j < 4; j++) acc[mt][nt][j] = 0.f;

    const int S = K >> 4;

    uint32_t ab[2], bb[2];
    ab[0] = (uint32_t)__cvta_generic_to_shared(&As[0][0]);
    ab[1] = (uint32_t)__cvta_generic_to_shared(&As[1][0]);
    bb[0] = (uint32_t)__cvta_generic_to_shared(&Bs[0][0]);
    bb[1] = (uint32_t)__cvta_generic_to_shared(&Bs[1][0]);

    auto stage = [&](int k0, uint32_t abase, uint32_t bbase) {
        #pragma unroll
        for (int i = 0; i < 2; i++) {
            int slot = tid + (i << 8);
            int m = slot >> 2, seg = slot & 3;
            int gr = rowTile + m; if (gr >= M) gr = M - 1;
            cp16(abase + (uint32_t)(m * AST + seg * 4) * 4,
                 A + (size_t)gr * K + k0 + seg * 4);
        }
        #pragma unroll
        for (int i = 0; i < 2; i++) {
            int slot = tid + (i << 8);
            int k = slot >> 5, seg = slot & 31;
            cp16(bbase + (uint32_t)(k * BST + seg * 4) * 4,
                 W + (size_t)(k0 + k) * 256 + colTile + seg * 4);
        }
    };

    stage(0, ab[0], bb[0]);
    cp_commit();

    for (int s = 0; s < S; s++) {
        const int buf = s & 1;
        if (s + 1 < S) {
            stage((s + 1) << 4, ab[buf ^ 1], bb[buf ^ 1]);
            cp_commit();
            asm volatile("cp.async.wait_group 1;");
        } else {
            asm volatile("cp.async.wait_group 0;");
        }
        __syncthreads();

        const float* as = As[buf];
        const float* bs = Bs[buf];

        #pragma unroll
        for (int k8 = 0; k8 < 2; k8++) {
            const int kk = k8 * 8;
            uint32_t ah[2][4], al[2][4];
            #pragma unroll
            for (int mt = 0; mt < 2; mt++)
                #pragma unroll
                for (int j = 0; j < 4; j++) {
                    int m = wm * 32 + mt * 16 + g + ((j & 1) << 3);
                    int k = kk + tig + ((j >> 1) << 2);
                    float v = as[m * AST + k];
                    uint32_t hi = cvt_tf32(v);
                    ah[mt][j] = hi;
                    al[mt][j] = cvt_tf32(v - __uint_as_float(hi));
                }
            uint32_t bh[8][2], bl[8][2];
            #pragma unroll
            for (int nt = 0; nt < 8; nt++)
                #pragma unroll
                for (int j = 0; j < 2; j++) {
                    int k = kk + tig + (j << 2);
                    int n = wn * 64 + nt * 8 + g;
                    float v = bs[k * BST + n];
                    uint32_t hi = cvt_tf32(v);
                    bh[nt][j] = hi;
                    bl[nt][j] = cvt_tf32(v - __uint_as_float(hi));
                }
            #pragma unroll
            for (int mt = 0; mt < 2; mt++)
                #pragma unroll
                for (int nt = 0; nt < 8; nt++) {
                    mma8(acc[mt][nt], ah[mt], bh[nt]);
                    mma8(acc[mt][nt], ah[mt], bl[nt]);
                    mma8(acc[mt][nt], al[mt], bh[nt]);
                }
        }
        __syncthreads();
    }

    #pragma unroll
    for (int mt = 0; mt < 2; mt++) {
        const int r0 = rowTile + wm * 32 + mt * 16 + g;
        const int r1 = r0 + 8;
        #pragma unroll
        for (int nt = 0; nt < 8; nt++) {
            const int col = colTile + wn * 64 + nt * 8 + tig * 2;
            float2 bv = *(const float2*)(bias + col);
            if (r0 < M) {
                float2 v;
                v.x = acc[mt][nt][0] + bv.x;
                v.y = acc[mt][nt][1] + bv.y;
                if (RELU) { v.x = fmaxf(v.x, 0.f); v.y = fmaxf(v.y, 0.f); }
                *(float2*)(C + (size_t)r0 * 256 + col) = v;
            }
            if (r1 < M) {
                float2 v;
                v.x = acc[mt][nt][2] + bv.x;
                v.y = acc[mt][nt][3] + bv.y;
                if (RELU) { v.x = fmaxf(v.x, 0.f); v.y = fmaxf(v.y, 0.f); }
                *(float2*)(C + (size_t)r1 * 256 + col) = v;
            }
        }
    }
}

// ---------------------------------------------------------------------------
// Edge-fused GEMM on dst-sorted edges. CTA tile 128(M edges) x 128(N), K=64.
// Fragment rows remapped so each thread owns 4 CONSECUTIVE sorted edges:
//   frag(mt, half) of lane-group g -> local edge 4g + 2*mt + half
// Epilogue: run-combine equal-dst edges in registers, then red.global.add.v4.
// ---------------------------------------------------------------------------
__global__ __launch_bounds__(256, 2)
void edge_gemm(const float* __restrict__ A, const float* __restrict__ W,
               const float* __restrict__ bias,
               const int* __restrict__ ei, const int* __restrict__ perm,
               const float* __restrict__ hg, float* __restrict__ agg)
{
    __shared__ float As[2][128 * AST];
    __shared__ float Bs[2][16 * BST];
    __shared__ int pidx[128];
    __shared__ int src_s[128];
    __shared__ int dst_s[128];

    const int tid  = threadIdx.x;
    const int lane = tid & 31;
    const int wid  = tid >> 5;
    const int g    = lane >> 2;
    const int tig  = lane & 3;
    const int wm   = wid & 3;     // 4 warps x 32 rows
    const int wn   = wid >> 2;    // 2 warps x 64 cols
    const int rowTile = blockIdx.y * 128;
    const int colTile = blockIdx.x * 128;

    if (tid < 128) {
        int pe = perm[rowTile + tid];
        pidx[tid] = pe;
        src_s[tid] = ei[pe];
        dst_s[tid] = ei[NE + pe];
    }
    __syncthreads();

    float acc[2][8][4];
    #pragma unroll
    for (int mt = 0; mt < 2; mt++)
        #pragma unroll
        for (int nt = 0; nt < 8; nt++)
            #pragma unroll
            for (int j = 0; j < 4; j++) acc[mt][nt][j] = 0.f;

    uint32_t ab[2], bb[2];
    ab[0] = (uint32_t)__cvta_generic_to_shared(&As[0][0]);
    ab[1] = (uint32_t)__cvta_generic_to_shared(&As[1][0]);
    bb[0] = (uint32_t)__cvta_generic_to_shared(&Bs[0][0]);
    bb[1] = (uint32_t)__cvta_generic_to_shared(&Bs[1][0]);

    auto stage = [&](int k0, uint32_t abase, uint32_t bbase) {
        // A: 128 rows x 16 k = 512 chunks -> 2 per thread (gather rows via perm)
        #pragma unroll
        for (int i = 0; i < 2; i++) {
            int slot = tid + (i << 8);
            int m = slot >> 2, seg = slot & 3;
            int pe = pidx[m];
            cp16(abase + (uint32_t)(m * AST + seg * 4) * 4,
                 A + (size_t)pe * 64 + k0 + seg * 4);
        }
        // B: 16 k x 128 n = 512 chunks -> 2 per thread
        #pragma unroll
        for (int i = 0; i < 2; i++) {
            int slot = tid + (i << 8);
            int k = slot >> 5, seg = slot & 31;
            cp16(bbase + (uint32_t)(k * BST + seg * 4) * 4,
                 W + (size_t)(k0 + k) * 256 + colTile + seg * 4);
        }
    };

    stage(0, ab[0], bb[0]);
    cp_commit();

    #pragma unroll
    for (int s = 0; s < 4; s++) {   // K = 64 -> 4 steps of 16
        const int buf = s & 1;
        if (s + 1 < 4) {
            stage((s + 1) << 4, ab[buf ^ 1], bb[buf ^ 1]);
            cp_commit();
            asm volatile("cp.async.wait_group 1;");
        } else {
            asm volatile("cp.async.wait_group 0;");
        }
        __syncthreads();

        const float* as = As[buf];
        const float* bs = Bs[buf];

        #pragma unroll
        for (int k8 = 0; k8 < 2; k8++) {
            const int kk = k8 * 8;
            uint32_t ah[2][4], al[2][4];
            #pragma unroll
            for (int mt = 0; mt < 2; mt++)
                #pragma unroll
                for (int j = 0; j < 4; j++) {
                    // frag row (g | g+8) -> consecutive sorted edge 4g+2mt+(j&1)
                    int m = wm * 32 + 4 * g + 2 * mt + (j & 1);
                    int k = kk + tig + ((j >> 1) << 2);
                    float v = as[m * AST + k];
                    uint32_t hi = cvt_tf32(v);
                    ah[mt][j] = hi;
                    al[mt][j] = cvt_tf32(v - __uint_as_float(hi));
                }
            uint32_t bh[8][2], bl[8][2];
            #pragma unroll
            for (int nt = 0; nt < 8; nt++)
                #pragma unroll
                for (int j = 0; j < 2; j++) {
                    int k = kk + tig + (j << 2);
                    int n = wn * 64 + nt * 8 + g;
                    float v = bs[k * BST + n];
                    uint32_t hi = cvt_tf32(v);
                    bh[nt][j] = hi;
                    bl[nt][j] = cvt_tf32(v - __uint_as_float(hi));
                }
            #pragma unroll
            for (int mt = 0; mt < 2; mt++)
                #pragma unroll
                for (int nt = 0; nt < 8; nt++) {
                    mma8(acc[mt][nt], ah[mt], bh[nt]);
                    mma8(acc[mt][nt], ah[mt], bl[nt]);
                    mma8(acc[mt][nt], al[mt], bh[nt]);
                }
        }
        __syncthreads();
    }

    // ---------------- fused epilogue: gather + relu + run-combined scatter ----
    const int eb = wm * 32 + 4 * g;        // this thread's 4 consecutive edges
    const int d0 = dst_s[eb + 0], d1 = dst_s[eb + 1];
    const int d2 = dst_s[eb + 2], d3 = dst_s[eb + 3];
    const int s0 = src_s[eb + 0], s1 = src_s[eb + 1];
    const int s2 = src_s[eb + 2], s3 = src_s[eb + 3];
    const bool even = (tig & 1) == 0;

    #pragma unroll
    for (int nt = 0; nt < 8; nt++) {
        // pair adjacent tig lanes: even lane assembles float4 over cols [col, col+4)
        float p[2][4];
        #pragma unroll
        for (int mt = 0; mt < 2; mt++)
            #pragma unroll
            for (int j = 0; j < 4; j++)
                p[mt][j] = __shfl_xor_sync(0xffffffffu, acc[mt][nt][j], 1);

        if (even) {
            const int col = colTile + wn * 64 + nt * 8 + tig * 2;
            float4 bv = *(const float4*)(bias + col);
            float4 v0, v1, v2, v3;
            v0.x = acc[0][nt][0] + bv.x; v0.y = acc[0][nt][1] + bv.y;
            v0.z = p[0][0] + bv.z;       v0.w = p[0][1] + bv.w;
            v1.x = acc[0][nt][2] + bv.x; v1.y = acc[0][nt][3] + bv.y;
            v1.z = p[0][2] + bv.z;       v1.w = p[0][3] + bv.w;
            v2.x = acc[1][nt][0] + bv.x; v2.y = acc[1][nt][1] + bv.y;
            v2.z = p[1][0] + bv.z;       v2.w = p[1][1] + bv.w;
            v3.x = acc[1][nt][2] + bv.x; v3.y = acc[1][nt][3] + bv.y;
            v3.z = p[1][2] + bv.z;       v3.w = p[1][3] + bv.w;

            float4 h0 = *(const float4*)(hg + (size_t)s0 * 256 + col);
            float4 h1 = *(const float4*)(hg + (size_t)s1 * 256 + col);
            float4 h2 = *(const float4*)(hg + (size_t)s2 * 256 + col);
            float4 h3 = *(const float4*)(hg + (size_t)s3 * 256 + col);

            v0.x = fmaxf(v0.x + h0.x, 0.f); v0.y = fmaxf(v0.y + h0.y, 0.f);
            v0.z = fmaxf(v0.z + h0.z, 0.f); v0.w = fmaxf(v0.w + h0.w, 0.f);
            v1.x = fmaxf(v1.x + h1.x, 0.f); v1.y = fmaxf(v1.y + h1.y, 0.f);
            v1.z = fmaxf(v1.z + h1.z, 0.f); v1.w = fmaxf(v1.w + h1.w, 0.f);
            v2.x = fmaxf(v2.x + h2.x, 0.f); v2.y = fmaxf(v2.y + h2.y, 0.f);
            v2.z = fmaxf(v2.z + h2.z, 0.f); v2.w = fmaxf(v2.w + h2.w, 0.f);
            v3.x = fmaxf(v3.x + h3.x, 0.f); v3.y = fmaxf(v3.y + h3.y, 0.f);
            v3.z = fmaxf(v3.z + h3.z, 0.f); v3.w = fmaxf(v3.w + h3.w, 0.f);

            // run-combine consecutive equal-dst edges, then scatter
            float4 cur = v0; int cd = d0;
            if (d1 == cd) {
                cur.x += v1.x; cur.y += v1.y; cur.z += v1.z; cur.w += v1.w;
            } else {
                red_add_v4(agg + (size_t)cd * 256 + col, cur);
                cur = v1; cd = d1;
            }
            if (d2 == cd) {
                cur.x += v2.x; cur.y += v2.y; cur.z += v2.z; cur.w += v2.w;
            } else {
                red_add_v4(agg + (size_t)cd * 256 + col, cur);
                cur = v2; cd = d2;
            }
            if (d3 == cd) {
                cur.x += v3.x; cur.y += v3.y; cur.z += v3.z; cur.w += v3.w;
            } else {
                red_add_v4(agg + (size_t)cd * 256 + col, cur);
                cur = v3; cd = d3;
            }
            red_add_v4(agg + (size_t)cd * 256 + col, cur);
        }
    }
}

// One block (64 threads) per node: scatter mean-pool contributions.
__global__ void pool_kernel(const float* __restrict__ h,
                            const int* __restrict__ batch,
                            float* __restrict__ pool, float* __restrict__ cnt)
{
    const int node = blockIdx.x;
    const int gph = batch[node];
    const int t = threadIdx.x;  // 0..63
    float4 v = *reinterpret_cast<const float4*>(h + (size_t)node * 256 + t * 4);
    red_add_v4(pool + (size_t)gph * 256 + t * 4, v);
    if (t == 0) atomicAdd(cnt + gph, 1.0f);
}

// One block per graph: mean -> relu(g@W1+b1)@W2+b2 -> L2 normalize.
__global__ void final_kernel(const float* __restrict__ pool,
                             const float* __restrict__ cnt,
                             const float* __restrict__ W1, const float* __restrict__ b1,
                             const float* __restrict__ W2, const float* __restrict__ b2,
                             float* __restrict__ out)
{
    const int gph = blockIdx.x;
    const int j = threadIdx.x;  // 0..255
    __shared__ float s[256];
    __shared__ float s2[256];
    __shared__ float redbuf[8];
    __shared__ float snorm;

    const float inv = 1.0f / fmaxf(cnt[gph], 1.0f);
    s[j] = pool[gph * 256 + j] * inv;
    __syncthreads();

    float t = b1[j];
    #pragma unroll 8
    for (int k = 0; k < 256; k++) t = fmaf(s[k], W1[k * 256 + j], t);
    t = fmaxf(t, 0.f);
    s2[j] = t;
    __syncthreads();

    float o = b2[j];
    #pragma unroll 8
    for (int k = 0; k < 256; k++) o = fmaf(s2[k], W2[k * 256 + j], o);

    float sq = o * o;
    #pragma unroll
    for (int off = 16; off > 0; off >>= 1)
        sq += __shfl_down_sync(0xffffffffu, sq, off);
    if ((j & 31) == 0) redbuf[j >> 5] = sq;
    __syncthreads();
    if (j == 0) {
        float ss = 0.f;
        #pragma unroll
        for (int w = 0; w < 8; w++) ss += redbuf[w];
        snorm = fmaxf(sqrtf(ss), 1e-12f);
    }
    __syncthreads();

    out[gph * 256 + j] = o / snorm;
}

extern "C" void kernel_launch(void* const* d_in, const int* in_sizes, int n_in,
                              void* d_out, int out_size)
{
    const float* x   = (const float*)d_in[0];
    const int*   ei  = (const int*)  d_in[1];
    const float* ea  = (const float*)d_in[2];
    const int*   bi  = (const int*)  d_in[3];
    const float* xW  = (const float*)d_in[4];
    const float* xb  = (const float*)d_in[5];
    const float* eW  = (const float*)d_in[6];
    const float* eb  = (const float*)d_in[7];
    const float* W1  = (const float*)d_in[8];
    const float* b1  = (const float*)d_in[9];
    const float* W2  = (const float*)d_in[10];
    const float* b2  = (const float*)d_in[11];
    const float* oW1 = (const float*)d_in[12];
    const float* ob1 = (const float*)d_in[13];
    const float* oW2 = (const float*)d_in[14];
    const float* ob2 = (const float*)d_in[15];
    float* out = (float*)d_out;

    float *ph, *pagg, *pt, *ppool, *pcnt;
    int *phisto, *pperm;
    cudaGetSymbolAddress((void**)&ph,    g_h);
    cudaGetSymbolAddress((void**)&pagg,  g_agg);
    cudaGetSymbolAddress((void**)&pt,    g_t);
    cudaGetSymbolAddress((void**)&ppool, g_pool);
    cudaGetSymbolAddress((void**)&pcnt,  g_cnt);
    cudaGetSymbolAddress((void**)&phisto, g_histo);
    cudaGetSymbolAddress((void**)&pperm,  g_perm);

    dim3 gNode(2, (NN + 127) / 128);   // (2, 157)
    dim3 gEdge(2, NE / 128);           // (2, 2500)

    // ---- counting sort of edges by dst (reused by all 3 layers) ----
    zero4<<<(NN / 4 + 255) / 256, 256>>>((float4*)phisto, NN / 4);
    hist_kernel<<<(NE + 255) / 256, 256>>>(ei, phisto);
    scan_kernel<<<1, 256>>>(phisto);
    scatter_kernel<<<(NE + 255) / 256, 256>>>(ei, phisto, pperm);

    // h = x @ xproj_W + xproj_b   (K = 128)
    mma_gemm<false><<<gNode, 256>>>(x, xW, xb, ph, NN, 128);

    for (int l = 0; l < 3; l++) {
        // agg = h  (folds the "+ x_i" of GIN into the scatter target)
        copy4<<<(NN * 64 + 255) / 256, 256>>>((const float4*)ph, (float4*)pagg, NN * 64);
        // fused: proj = ea @ eW[l] + eb[l]; msg = relu(h[src] + proj); agg[dst] += msg
        edge_gemm<<<gEdge, 256>>>(ea, eW + l * 64 * 256, eb + l * 256, ei, pperm, ph, pagg);
        // t = relu(agg @ W1 + b1)   (K = 256)
        mma_gemm<true><<<gNode, 256>>>(pagg, W1 + l * 256 * 256, b1 + l * 256, pt, NN, 256);
        // h = relu(t @ W2 + b2)
        mma_gemm<true><<<gNode, 256>>>(pt, W2 + l * 256 * 256, b2 + l * 256, ph, NN, 256);
    }

    // mean pool
    zero4<<<(NG * 64 + 255) / 256, 256>>>((float4*)ppool, NG * 64);
    zero4<<<1, 256>>>((float4*)pcnt, NG / 4);
    pool_kernel<<<NN, 64>>>(ph, bi, ppool, pcnt);

    // graph head + normalize
    final_kernel<<<NG, 256>>>(ppool, pcnt, oW1, ob1, oW2, ob2, out);
}